// round 5
// baseline (speedup 1.0000x reference)
#include <cuda_runtime.h>
#include <cuda_bf16.h>
#include <cstdint>

// ----------------------------------------------------------------------------
// DPO loss on GB300 (sm_103 base target — legacy mma.sync path).
// Round 5: int8 IMMA (m16n8k32, s32 accum) — 2x MACs/instruction vs bf16 HMMA.
// Per-row symmetric quantization; exact fp32 token logits; fused online LSE.
// ----------------------------------------------------------------------------

#define BM 128
#define BN 128
#define KC 128                // K int8 per stage: 128B rows (SW128 swizzle)
#define NSTAGE 3

static constexpr int Hdim   = 4096;
static constexpr int Mtot   = 4096;          // 8*512 tokens
static constexpr int Vdim   = 32000;
static constexpr int NT_PER = Vdim / BN;     // 250 N-tiles per matrix
static constexpr int NT_TOT = 2 * NT_PER;    // 500
static constexpr int NKT    = Hdim / KC;     // 32 k-chunks

static constexpr int A_BYTES  = BM * 128;    // 16 KB
static constexpr int B_BYTES  = BN * 128;    // 16 KB
static constexpr int STAGE_B  = A_BYTES + B_BYTES;          // 32 KB
static constexpr int DSMEM    = 1024 + NSTAGE * STAGE_B;    // ~97 KB

// ---------------- scratch (allocation-free __device__ globals) ----------------
__device__ int8_t g_xq[(size_t)Mtot * Hdim];   //  16.8 MB
__device__ int8_t g_wq[(size_t)Vdim * Hdim];   // 131 MB
__device__ int8_t g_rq[(size_t)Vdim * Hdim];   // 131 MB
__device__ float  g_sx[Mtot];
__device__ float  g_sw[Vdim];
__device__ float  g_sr[Vdim];
__device__ float  g_pmax[NT_TOT * Mtot];
__device__ float  g_psum[NT_TOT * Mtot];
__device__ float  g_tokW[Mtot];
__device__ float  g_tokR[Mtot];
__device__ float  g_lzW[Mtot];
__device__ float  g_lzR[Mtot];
__device__ int    g_y_is64;

__device__ __forceinline__ uint32_t smem_u32(const void* p) {
    return (uint32_t)__cvta_generic_to_shared(p);
}
__device__ __forceinline__ void cp_async16(uint32_t dst, const void* src) {
    asm volatile("cp.async.cg.shared.global [%0], [%1], 16;\n" :: "r"(dst), "l"(src));
}
#define SWZ(x) ((x) ^ (((x) >> 3) & 0x70))

// label accessor, safe under int32 or int64 storage
__device__ __forceinline__ int get_label(const void* y, int m) {
    if (g_y_is64) return (int)((const long long*)y)[m];
    return ((const int*)y)[m];
}

// ----------------------------------------------------------------------------
__global__ void detect_y_kernel(const int* __restrict__ y32)
{
    if (threadIdx.x == 0) {
        int is64 = 1;
        for (int i = 0; i < 64; i++) {
            int hi = y32[2 * i + 1];
            if (hi != 0 && hi != -1) { is64 = 0; break; }
        }
        g_y_is64 = is64;
    }
}

// ----------------------------------------------------------------------------
// fp32 -> int8 per-row quantization. One block (256 thr) per 4096-elem row.
// Single pass: row held in registers (16 floats/thread).
// ----------------------------------------------------------------------------
__global__ __launch_bounds__(256) void quant_kernel(const float* __restrict__ src,
                                                    int which)
{
    int8_t* dst = (which == 0) ? g_xq : (which == 1) ? g_wq : g_rq;
    float*  scl = (which == 0) ? g_sx : (which == 1) ? g_sw : g_sr;

    const int row = blockIdx.x;
    const int tid = threadIdx.x;
    const float4* s = reinterpret_cast<const float4*>(src + (size_t)row * Hdim);

    float4 v[4];
    float mx = 0.f;
#pragma unroll
    for (int i = 0; i < 4; i++) {
        v[i] = s[tid + i * 256];
        mx = fmaxf(mx, fmaxf(fmaxf(fabsf(v[i].x), fabsf(v[i].y)),
                             fmaxf(fabsf(v[i].z), fabsf(v[i].w))));
    }
    // block max
    __shared__ float wmax[8];
#pragma unroll
    for (int o = 16; o > 0; o >>= 1)
        mx = fmaxf(mx, __shfl_xor_sync(0xffffffffu, mx, o));
    if ((tid & 31) == 0) wmax[tid >> 5] = mx;
    __syncthreads();
    float bm = fmaxf(fmaxf(fmaxf(wmax[0], wmax[1]), fmaxf(wmax[2], wmax[3])),
                     fmaxf(fmaxf(wmax[4], wmax[5]), fmaxf(wmax[6], wmax[7])));
    bm = fmaxf(bm, 1e-20f);
    const float scale = bm / 127.f;
    const float inv   = 127.f / bm;

#pragma unroll
    for (int i = 0; i < 4; i++) {
        int a = __float2int_rn(v[i].x * inv);
        int b = __float2int_rn(v[i].y * inv);
        int c = __float2int_rn(v[i].z * inv);
        int d = __float2int_rn(v[i].w * inv);
        a = max(-127, min(127, a)); b = max(-127, min(127, b));
        c = max(-127, min(127, c)); d = max(-127, min(127, d));
        char4 q = make_char4((char)a, (char)b, (char)c, (char)d);
        *reinterpret_cast<char4*>(dst + (size_t)row * Hdim + (tid + i * 256) * 4) = q;
    }
    if (tid == 0) scl[row] = scale;
}

// ----------------------------------------------------------------------------
// Main int8 GEMM + online LSE epilogue. grid=(32 mt [fast], 500 nt), block=256.
// 8 warps in 2x4 (M x N); each warp computes 64x32. acc in s32 (exact).
// ----------------------------------------------------------------------------
__global__ __launch_bounds__(256, 2) void lse_kernel()
{
    extern __shared__ char dsm[];
    const uint32_t raw = smem_u32(dsm);
    const uint32_t stg = (raw + 1023) & ~1023u;

    __shared__ float s_red[BM * 4];
    __shared__ float s_rowmax[BM];
    __shared__ float s_sw[BN];

    const int tid  = threadIdx.x;
    const int warp = tid >> 5, lane = tid & 31;
    const int wm   = warp >> 2, wn = warp & 3;

    const int mt = blockIdx.x, nt = blockIdx.y;
    const int m0 = mt * BM;
    const int n0 = (nt < NT_PER ? nt : nt - NT_PER) * BN;
    const int8_t* asrc = g_xq + (size_t)m0 * Hdim;
    const int8_t* bsrc = ((nt < NT_PER) ? g_wq : g_rq) + (size_t)n0 * Hdim;
    const float* swsrc = ((nt < NT_PER) ? g_sw : g_sr) + n0;

    // col scales for this tile (sync provided by mainloop's first __syncthreads)
    if (tid < BN) s_sw[tid] = swsrc[tid];

    int acc[4][4][4];
#pragma unroll
    for (int i = 0; i < 4; i++)
#pragma unroll
        for (int j = 0; j < 4; j++)
#pragma unroll
            for (int c = 0; c < 4; c++) acc[i][j][c] = 0;

    auto load_stage = [&](int slot, int kt) {
        const uint32_t a_base = stg + slot * STAGE_B;
        const uint32_t b_base = a_base + A_BYTES;
        const int k0 = kt * KC;
#pragma unroll
        for (int i = 0; i < 4; i++) {
            int id  = tid + i * 256;          // 0..1023
            int row = id >> 3, c = id & 7;    // 128 rows x 8 x 16B chunks
            cp_async16(a_base + SWZ(row * 128 + c * 16),
                       asrc + (size_t)row * Hdim + k0 + c * 16);
            cp_async16(b_base + SWZ(row * 128 + c * 16),
                       bsrc + (size_t)row * Hdim + k0 + c * 16);
        }
        asm volatile("cp.async.commit_group;" ::: "memory");
    };

    auto compute = [&](int slot) {
        const uint32_t a_base = stg + slot * STAGE_B;
        const uint32_t b_base = a_base + A_BYTES;
#pragma unroll
        for (int ks = 0; ks < 4; ks++) {       // 4 x K=32(int8) inside 128B chunk
            uint32_t af[4][4], bf[4][2];
            const int arow = wm * 64 + (lane & 15);
            const int asel = (lane >> 4) & 1;
#pragma unroll
            for (int mi = 0; mi < 4; mi++) {
                uint32_t addr = a_base +
                    SWZ((uint32_t)(arow + mi * 16) * 128 + ks * 32 + asel * 16);
                asm volatile("ldmatrix.sync.aligned.m8n8.x4.shared.b16 {%0,%1,%2,%3}, [%4];"
                             : "=r"(af[mi][0]), "=r"(af[mi][1]),
                               "=r"(af[mi][2]), "=r"(af[mi][3])
                             : "r"(addr));
            }
            const int brow = wn * 32 + (lane & 7);
            const int bsel = (lane >> 3) & 1;
#pragma unroll
            for (int ni = 0; ni < 4; ni++) {
                uint32_t addr = b_base +
                    SWZ((uint32_t)(brow + ni * 8) * 128 + ks * 32 + bsel * 16);
                asm volatile("ldmatrix.sync.aligned.m8n8.x2.shared.b16 {%0,%1}, [%2];"
                             : "=r"(bf[ni][0]), "=r"(bf[ni][1])
                             : "r"(addr));
            }
#pragma unroll
            for (int mi = 0; mi < 4; mi++)
#pragma unroll
                for (int ni = 0; ni < 4; ni++)
                    asm volatile(
                        "mma.sync.aligned.m16n8k32.row.col.s32.s8.s8.s32 "
                        "{%0,%1,%2,%3}, {%4,%5,%6,%7}, {%8,%9}, {%0,%1,%2,%3};"
                        : "+r"(acc[mi][ni][0]), "+r"(acc[mi][ni][1]),
                          "+r"(acc[mi][ni][2]), "+r"(acc[mi][ni][3])
                        : "r"(af[mi][0]), "r"(af[mi][1]), "r"(af[mi][2]), "r"(af[mi][3]),
                          "r"(bf[ni][0]), "r"(bf[ni][1]));
        }
    };

    load_stage(0, 0);
    load_stage(1, 1);

    for (int kt = 0; kt < NKT; kt++) {
        const int slot = kt % NSTAGE;
        if (kt + 2 < NKT) {
            asm volatile("cp.async.wait_group 1;" ::: "memory");
        } else {
            asm volatile("cp.async.wait_group 0;" ::: "memory");
        }
        __syncthreads();
        if (kt + 2 < NKT) load_stage((kt + 2) % NSTAGE, kt + 2);
        compute(slot);
    }

    // ---- dequantize in place: acc <- float bits of sx*sw*acc ----
#pragma unroll
    for (int mi = 0; mi < 4; mi++) {
        const int rlo = wm * 64 + mi * 16 + (lane >> 2);
        const float sxlo = g_sx[m0 + rlo];
        const float sxhi = g_sx[m0 + rlo + 8];
#pragma unroll
        for (int ni = 0; ni < 4; ni++) {
            const int col0 = wn * 32 + ni * 8 + (lane & 3) * 2;
            const float sw0 = s_sw[col0], sw1 = s_sw[col0 + 1];
            acc[mi][ni][0] = __float_as_int((float)acc[mi][ni][0] * sxlo * sw0);
            acc[mi][ni][1] = __float_as_int((float)acc[mi][ni][1] * sxlo * sw1);
            acc[mi][ni][2] = __float_as_int((float)acc[mi][ni][2] * sxhi * sw0);
            acc[mi][ni][3] = __float_as_int((float)acc[mi][ni][3] * sxhi * sw1);
        }
    }

    // ---- fused epilogue: per-token max / sumexp over this 128-col tile ----
    const float NEG = -1e30f;
#pragma unroll
    for (int mi = 0; mi < 4; mi++) {
        float mlo = NEG, mhi = NEG;
#pragma unroll
        for (int ni = 0; ni < 4; ni++) {
            mlo = fmaxf(mlo, fmaxf(__int_as_float(acc[mi][ni][0]),
                                   __int_as_float(acc[mi][ni][1])));
            mhi = fmaxf(mhi, fmaxf(__int_as_float(acc[mi][ni][2]),
                                   __int_as_float(acc[mi][ni][3])));
        }
#pragma unroll
        for (int o = 1; o < 4; o <<= 1) {
            mlo = fmaxf(mlo, __shfl_xor_sync(0xffffffffu, mlo, o));
            mhi = fmaxf(mhi, __shfl_xor_sync(0xffffffffu, mhi, o));
        }
        if ((lane & 3) == 0) {
            int rlo = wm * 64 + mi * 16 + (lane >> 2);
            s_red[rlo * 4 + wn]       = mlo;
            s_red[(rlo + 8) * 4 + wn] = mhi;
        }
    }
    __syncthreads();
    if (tid < BM) {
        s_rowmax[tid] = fmaxf(fmaxf(s_red[tid * 4 + 0], s_red[tid * 4 + 1]),
                              fmaxf(s_red[tid * 4 + 2], s_red[tid * 4 + 3]));
    }
    __syncthreads();
#pragma unroll
    for (int mi = 0; mi < 4; mi++) {
        int rlo = wm * 64 + mi * 16 + (lane >> 2);
        int rhi = rlo + 8;
        float Mlo = s_rowmax[rlo], Mhi = s_rowmax[rhi];
        float slo = 0.f, shi = 0.f;
#pragma unroll
        for (int ni = 0; ni < 4; ni++) {
            slo += __expf(__int_as_float(acc[mi][ni][0]) - Mlo)
                 + __expf(__int_as_float(acc[mi][ni][1]) - Mlo);
            shi += __expf(__int_as_float(acc[mi][ni][2]) - Mhi)
                 + __expf(__int_as_float(acc[mi][ni][3]) - Mhi);
        }
#pragma unroll
        for (int o = 1; o < 4; o <<= 1) {
            slo += __shfl_xor_sync(0xffffffffu, slo, o);
            shi += __shfl_xor_sync(0xffffffffu, shi, o);
        }
        if ((lane & 3) == 0) {
            s_red[rlo * 4 + wn] = slo;
            s_red[rhi * 4 + wn] = shi;
        }
    }
    __syncthreads();
    if (tid < BM) {
        float s = s_red[tid * 4 + 0] + s_red[tid * 4 + 1] +
                  s_red[tid * 4 + 2] + s_red[tid * 4 + 3];
        g_pmax[(size_t)nt * Mtot + m0 + tid] = s_rowmax[tid];
        g_psum[(size_t)nt * Mtot + m0 + tid] = s;
    }
}

// ----------------------------------------------------------------------------
// Combine per-tile partials -> logZ per token, per matrix. grid=4096, block=256
// ----------------------------------------------------------------------------
__global__ void reduce_lz_kernel()
{
    __shared__ float sm[256];
    __shared__ float ss[256];
    const int m = blockIdx.x, tid = threadIdx.x;
#pragma unroll
    for (int mat = 0; mat < 2; mat++) {
        const int base = mat * NT_PER;
        float mx = -1e30f, sv = 0.f;
        if (tid < NT_PER) {
            mx = g_pmax[(size_t)(base + tid) * Mtot + m];
            sv = g_psum[(size_t)(base + tid) * Mtot + m];
        }
        sm[tid] = mx; __syncthreads();
        for (int s = 128; s > 0; s >>= 1) {
            if (tid < s) sm[tid] = fmaxf(sm[tid], sm[tid + s]);
            __syncthreads();
        }
        const float M = sm[0];
        ss[tid] = (tid < NT_PER) ? sv * expf(mx - M) : 0.f;
        __syncthreads();
        for (int s = 128; s > 0; s >>= 1) {
            if (tid < s) ss[tid] += ss[tid + s];
            __syncthreads();
        }
        if (tid == 0) {
            float lz = M + logf(ss[0]);
            if (mat == 0) g_lzW[m] = lz; else g_lzR[m] = lz;
        }
        __syncthreads();
    }
}

// ----------------------------------------------------------------------------
// Exact fp32 token logits: one warp per token. grid=1024, block=128
// ----------------------------------------------------------------------------
__global__ void tok_kernel(const float* __restrict__ x,
                           const float* __restrict__ W,
                           const float* __restrict__ refW,
                           const void* __restrict__ y)
{
    const int warp = threadIdx.x >> 5, lane = threadIdx.x & 31;
    const int m = blockIdx.x * 4 + warp;
    int idx = get_label(y, m);
    if (idx < 0 || idx >= Vdim) idx = 0;     // defensive clamp
    const float4* xr = reinterpret_cast<const float4*>(x    + (size_t)m   * Hdim);
    const float4* wr = reinterpret_cast<const float4*>(W    + (size_t)idx * Hdim);
    const float4* rr = reinterpret_cast<const float4*>(refW + (size_t)idx * Hdim);
    float sw = 0.f, sr = 0.f;
    for (int j = lane; j < Hdim / 4; j += 32) {
        float4 a = xr[j], b = wr[j], c = rr[j];
        sw += a.x * b.x + a.y * b.y + a.z * b.z + a.w * b.w;
        sr += a.x * c.x + a.y * c.y + a.z * c.z + a.w * c.w;
    }
#pragma unroll
    for (int o = 16; o > 0; o >>= 1) {
        sw += __shfl_xor_sync(0xffffffffu, sw, o);
        sr += __shfl_xor_sync(0xffffffffu, sr, o);
    }
    if (lane == 0) { g_tokW[m] = sw; g_tokR[m] = sr; }
}

// ----------------------------------------------------------------------------
// Final DPO scalar. one block of 512
// ----------------------------------------------------------------------------
__global__ void final_kernel(const void* __restrict__ y, float* __restrict__ out)
{
    __shared__ float red[512];
    __shared__ float pav[8], rav[8];
    const int tid = threadIdx.x;
    for (int b = 0; b < 8; b++) {
        const int m = b * 512 + tid;
        const int yv = get_label(y, m);
        const bool v = (yv != -100);
        const float p = v ? (g_tokW[m] - g_lzW[m]) : 0.f;
        const float r = v ? (g_tokR[m] - g_lzR[m]) : 0.f;
        const float c = v ? 1.f : 0.f;

        red[tid] = p; __syncthreads();
        for (int s = 256; s > 0; s >>= 1) { if (tid < s) red[tid] += red[tid + s]; __syncthreads(); }
        float ps = red[0]; __syncthreads();

        red[tid] = r; __syncthreads();
        for (int s = 256; s > 0; s >>= 1) { if (tid < s) red[tid] += red[tid + s]; __syncthreads(); }
        float rs = red[0]; __syncthreads();

        red[tid] = c; __syncthreads();
        for (int s = 256; s > 0; s >>= 1) { if (tid < s) red[tid] += red[tid + s]; __syncthreads(); }
        float cs = red[0]; __syncthreads();

        if (tid == 0) { pav[b] = ps / cs; rav[b] = rs / cs; }
        __syncthreads();
    }
    if (tid == 0) {
        float loss = 0.f;
#pragma unroll
        for (int i = 0; i < 4; i++) {
            float z = 0.1f * ((pav[i] - rav[i]) - (pav[i + 4] - rav[i + 4]));
            loss += log1pf(expf(-z));
        }
        out[0] = loss * 0.25f;
    }
}

// ----------------------------------------------------------------------------
extern "C" void kernel_launch(void* const* d_in, const int* in_sizes, int n_in,
                              void* d_out, int out_size)
{
    const float* x = nullptr;
    const void*  y = nullptr;
    const float* Wm[2] = {nullptr, nullptr};
    int wcount = 0;
    for (int i = 0; i < n_in; i++) {
        if (in_sizes[i] == 16777216)                          x = (const float*)d_in[i];
        else if (in_sizes[i] == 4096 || in_sizes[i] == 8192)  y = d_in[i];
        else if (wcount < 2)                                  Wm[wcount++] = (const float*)d_in[i];
    }
    if (!x)      x     = (const float*)d_in[0];
    if (!y)      y     = d_in[1];
    if (!Wm[0])  Wm[0] = (const float*)d_in[2];
    if (!Wm[1])  Wm[1] = (const float*)d_in[3];
    const float* W    = Wm[0];
    const float* refW = Wm[1];

    cudaFuncSetAttribute(lse_kernel, cudaFuncAttributeMaxDynamicSharedMemorySize, DSMEM);

    detect_y_kernel<<<1, 32>>>((const int*)y);
    quant_kernel<<<Mtot, 256>>>(x,    0);
    quant_kernel<<<Vdim, 256>>>(W,    1);
    quant_kernel<<<Vdim, 256>>>(refW, 2);

    dim3 grid(Mtot / BM, NT_TOT);   // (32 [fast: x L2-resident], 500)
    lse_kernel<<<grid, 256, DSMEM>>>();

    reduce_lz_kernel<<<Mtot, 256>>>();
    tok_kernel<<<Mtot / 4, 128>>>(x, W, refW, y);
    final_kernel<<<1, 512>>>(y, (float*)d_out);
}

// round 6
// speedup vs baseline: 4.9132x; 4.9132x over previous
#include <cuda_runtime.h>
#include <cuda_bf16.h>
#include <cstdint>

// ----------------------------------------------------------------------------
// DPO loss on GB300 (sm_103 base target — legacy bf16 HMMA path, ~300 TF/s).
// Round 6: R4 design + single merged convert launch (puts lse_kernel in the
// ncu capture window) + B-ldmatrix x4 (fewer LDSM issue slots).
// ----------------------------------------------------------------------------

#define BM 128
#define BN 128
#define KC 64                 // K elems per stage: 128B rows (SW128 swizzle)
#define NSTAGE 3

static constexpr int Hdim   = 4096;
static constexpr int Mtot   = 4096;          // 8*512 tokens
static constexpr int Vdim   = 32000;
static constexpr int NT_PER = Vdim / BN;     // 250 N-tiles per matrix
static constexpr int NT_TOT = 2 * NT_PER;    // 500
static constexpr int NKT    = Hdim / KC;     // 64 k-chunks

static constexpr int A_BYTES  = BM * 128;    // 16 KB
static constexpr int B_BYTES  = BN * 128;    // 16 KB
static constexpr int STAGE_B  = A_BYTES + B_BYTES;          // 32 KB
static constexpr int DSMEM    = 1024 + NSTAGE * STAGE_B;    // ~97 KB

// ---------------- scratch (allocation-free __device__ globals) ----------------
__device__ __nv_bfloat16 g_xbf[(size_t)Mtot * Hdim];   //  33.5 MB
__device__ __nv_bfloat16 g_wbf[(size_t)Vdim * Hdim];   // 262 MB
__device__ __nv_bfloat16 g_rbf[(size_t)Vdim * Hdim];   // 262 MB
__device__ float g_pmax[NT_TOT * Mtot];
__device__ float g_psum[NT_TOT * Mtot];
__device__ float g_tokW[Mtot];
__device__ float g_tokR[Mtot];
__device__ float g_lzW[Mtot];
__device__ float g_lzR[Mtot];
__device__ int   g_y_is64;

__device__ __forceinline__ uint32_t smem_u32(const void* p) {
    return (uint32_t)__cvta_generic_to_shared(p);
}
__device__ __forceinline__ void cp_async16(uint32_t dst, const void* src) {
    asm volatile("cp.async.cg.shared.global [%0], [%1], 16;\n" :: "r"(dst), "l"(src));
}
#define SWZ(x) ((x) ^ (((x) >> 3) & 0x70))

// label accessor, safe under int32 or int64 storage
__device__ __forceinline__ int get_label(const void* y, int m) {
    if (g_y_is64) return (int)((const long long*)y)[m];
    return ((const int*)y)[m];
}

// ----------------------------------------------------------------------------
__global__ void detect_y_kernel(const int* __restrict__ y32)
{
    if (threadIdx.x == 0) {
        int is64 = 1;
        for (int i = 0; i < 64; i++) {
            int hi = y32[2 * i + 1];
            if (hi != 0 && hi != -1) { is64 = 0; break; }
        }
        g_y_is64 = is64;
    }
}

// ----------------------------------------------------------------------------
// Single merged fp32 -> bf16 convert over x, W, ref_W (one launch).
// ----------------------------------------------------------------------------
static constexpr size_t N8_X = (size_t)Mtot * Hdim / 8;          //  2,097,152
static constexpr size_t N8_W = (size_t)Vdim * Hdim / 8;          // 16,384,000
static constexpr size_t N8_TOT = N8_X + 2 * N8_W;

__global__ __launch_bounds__(256) void convert_all_kernel(
    const float* __restrict__ x, const float* __restrict__ W,
    const float* __restrict__ R)
{
    size_t i = (size_t)blockIdx.x * blockDim.x + threadIdx.x;
    const size_t stride = (size_t)gridDim.x * blockDim.x;
    for (; i < N8_TOT; i += stride) {
        const float* src;
        __nv_bfloat16* dst;
        size_t j;
        if (i < N8_X)               { src = x; dst = g_xbf; j = i; }
        else if (i < N8_X + N8_W)   { src = W; dst = g_wbf; j = i - N8_X; }
        else                        { src = R; dst = g_rbf; j = i - N8_X - N8_W; }
        const float4* s = reinterpret_cast<const float4*>(src) + 2 * j;
        float4 a = s[0], b = s[1];
        __nv_bfloat162 o[4] = {
            __floats2bfloat162_rn(a.x, a.y), __floats2bfloat162_rn(a.z, a.w),
            __floats2bfloat162_rn(b.x, b.y), __floats2bfloat162_rn(b.z, b.w)};
        *reinterpret_cast<uint4*>(dst + j * 8) = *reinterpret_cast<const uint4*>(o);
    }
}

// ----------------------------------------------------------------------------
// Main GEMM + online LSE epilogue. grid=(32 mt [fast], 500 nt), block=256.
// 8 warps in a 2x4 (M x N) grid; each warp computes 64x32.
// ----------------------------------------------------------------------------
__global__ __launch_bounds__(256, 2) void lse_kernel()
{
    extern __shared__ char dsm[];
    const uint32_t raw  = smem_u32(dsm);
    const uint32_t stg  = (raw + 1023) & ~1023u;   // 1024-aligned

    __shared__ float s_red[BM * 4];
    __shared__ float s_rowmax[BM];

    const int tid  = threadIdx.x;
    const int warp = tid >> 5, lane = tid & 31;
    const int wm   = warp >> 2, wn = warp & 3;

    const int mt = blockIdx.x, nt = blockIdx.y;
    const int m0 = mt * BM;
    const int n0 = (nt < NT_PER ? nt : nt - NT_PER) * BN;
    const __nv_bfloat16* asrc = g_xbf + (size_t)m0 * Hdim;
    const __nv_bfloat16* bsrc = ((nt < NT_PER) ? g_wbf : g_rbf) + (size_t)n0 * Hdim;

    float acc[4][4][4];
#pragma unroll
    for (int i = 0; i < 4; i++)
#pragma unroll
        for (int j = 0; j < 4; j++)
#pragma unroll
            for (int c = 0; c < 4; c++) acc[i][j][c] = 0.f;

    auto load_stage = [&](int slot, int kt) {
        const uint32_t a_base = stg + slot * STAGE_B;
        const uint32_t b_base = a_base + A_BYTES;
        const int k0 = kt * KC;
#pragma unroll
        for (int i = 0; i < 4; i++) {
            int id  = tid + i * 256;          // 0..1023
            int row = id >> 3, c = id & 7;    // 128 rows x 8 chunks
            cp_async16(a_base + SWZ(row * 128 + c * 16),
                       asrc + (size_t)row * Hdim + k0 + c * 8);
            cp_async16(b_base + SWZ(row * 128 + c * 16),
                       bsrc + (size_t)row * Hdim + k0 + c * 8);
        }
        asm volatile("cp.async.commit_group;" ::: "memory");
    };

    auto compute = [&](int slot) {
        const uint32_t a_base = stg + slot * STAGE_B;
        const uint32_t b_base = a_base + A_BYTES;
#pragma unroll
        for (int ks = 0; ks < 4; ks++) {       // 4 x K=16 inside the 64 chunk
            uint32_t af[4][4], bf[4][2];
            const int arow = wm * 64 + (lane & 15);
            const int asel = (lane >> 4) & 1;
#pragma unroll
            for (int mi = 0; mi < 4; mi++) {
                uint32_t addr = a_base +
                    SWZ((uint32_t)(arow + mi * 16) * 128 + ks * 32 + asel * 16);
                asm volatile("ldmatrix.sync.aligned.m8n8.x4.shared.b16 {%0,%1,%2,%3}, [%4];"
                             : "=r"(af[mi][0]), "=r"(af[mi][1]),
                               "=r"(af[mi][2]), "=r"(af[mi][3])
                             : "r"(addr));
            }
            // B: x4 over pairs of n-groups.
            // lanes 0-7:(ni,k0) 8-15:(ni,k1) 16-23:(ni+1,k0) 24-31:(ni+1,k1)
#pragma unroll
            for (int np = 0; np < 2; np++) {
                const uint32_t brow = wn * 32 + np * 16 +
                                      ((lane >> 4) << 3) + (lane & 7);
                const uint32_t bsel = (lane >> 3) & 1;
                uint32_t addr = b_base +
                    SWZ(brow * 128 + ks * 32 + bsel * 16);
                asm volatile("ldmatrix.sync.aligned.m8n8.x4.shared.b16 {%0,%1,%2,%3}, [%4];"
                             : "=r"(bf[2 * np][0]), "=r"(bf[2 * np][1]),
                               "=r"(bf[2 * np + 1][0]), "=r"(bf[2 * np + 1][1])
                             : "r"(addr));
            }
#pragma unroll
            for (int mi = 0; mi < 4; mi++)
#pragma unroll
                for (int ni = 0; ni < 4; ni++)
                    asm volatile(
                        "mma.sync.aligned.m16n8k16.row.col.f32.bf16.bf16.f32 "
                        "{%0,%1,%2,%3}, {%4,%5,%6,%7}, {%8,%9}, {%0,%1,%2,%3};"
                        : "+f"(acc[mi][ni][0]), "+f"(acc[mi][ni][1]),
                          "+f"(acc[mi][ni][2]), "+f"(acc[mi][ni][3])
                        : "r"(af[mi][0]), "r"(af[mi][1]), "r"(af[mi][2]), "r"(af[mi][3]),
                          "r"(bf[ni][0]), "r"(bf[ni][1]));
        }
    };

    // prologue: fill NSTAGE-1 stages
    load_stage(0, 0);
    load_stage(1, 1);

    for (int kt = 0; kt < NKT; kt++) {
        const int slot = kt % NSTAGE;
        if (kt + 2 < NKT) {
            asm volatile("cp.async.wait_group 1;" ::: "memory");
        } else {
            asm volatile("cp.async.wait_group 0;" ::: "memory");
        }
        __syncthreads();
        if (kt + 2 < NKT) load_stage((kt + 2) % NSTAGE, kt + 2);
        compute(slot);
    }

    // ---- fused epilogue: per-token max / sumexp over this 128-col tile ----
    const float NEG = -1e30f;
#pragma unroll
    for (int mi = 0; mi < 4; mi++) {
        float mlo = NEG, mhi = NEG;
#pragma unroll
        for (int ni = 0; ni < 4; ni++) {
            mlo = fmaxf(mlo, fmaxf(acc[mi][ni][0], acc[mi][ni][1]));
            mhi = fmaxf(mhi, fmaxf(acc[mi][ni][2], acc[mi][ni][3]));
        }
#pragma unroll
        for (int o = 1; o < 4; o <<= 1) {
            mlo = fmaxf(mlo, __shfl_xor_sync(0xffffffffu, mlo, o));
            mhi = fmaxf(mhi, __shfl_xor_sync(0xffffffffu, mhi, o));
        }
        if ((lane & 3) == 0) {
            int rlo = wm * 64 + mi * 16 + (lane >> 2);
            s_red[rlo * 4 + wn]       = mlo;
            s_red[(rlo + 8) * 4 + wn] = mhi;
        }
    }
    __syncthreads();
    if (tid < BM) {
        s_rowmax[tid] = fmaxf(fmaxf(s_red[tid * 4 + 0], s_red[tid * 4 + 1]),
                              fmaxf(s_red[tid * 4 + 2], s_red[tid * 4 + 3]));
    }
    __syncthreads();
#pragma unroll
    for (int mi = 0; mi < 4; mi++) {
        int rlo = wm * 64 + mi * 16 + (lane >> 2);
        int rhi = rlo + 8;
        float Mlo = s_rowmax[rlo], Mhi = s_rowmax[rhi];
        float slo = 0.f, shi = 0.f;
#pragma unroll
        for (int ni = 0; ni < 4; ni++) {
            slo += __expf(acc[mi][ni][0] - Mlo) + __expf(acc[mi][ni][1] - Mlo);
            shi += __expf(acc[mi][ni][2] - Mhi) + __expf(acc[mi][ni][3] - Mhi);
        }
#pragma unroll
        for (int o = 1; o < 4; o <<= 1) {
            slo += __shfl_xor_sync(0xffffffffu, slo, o);
            shi += __shfl_xor_sync(0xffffffffu, shi, o);
        }
        if ((lane & 3) == 0) {
            s_red[rlo * 4 + wn] = slo;
            s_red[rhi * 4 + wn] = shi;
        }
    }
    __syncthreads();
    if (tid < BM) {
        float s = s_red[tid * 4 + 0] + s_red[tid * 4 + 1] +
                  s_red[tid * 4 + 2] + s_red[tid * 4 + 3];
        g_pmax[(size_t)nt * Mtot + m0 + tid] = s_rowmax[tid];
        g_psum[(size_t)nt * Mtot + m0 + tid] = s;
    }
}

// ----------------------------------------------------------------------------
// Combine per-tile partials -> logZ per token, per matrix. grid=4096, block=256
// ----------------------------------------------------------------------------
__global__ void reduce_lz_kernel()
{
    __shared__ float sm[256];
    __shared__ float ss[256];
    const int m = blockIdx.x, tid = threadIdx.x;
#pragma unroll
    for (int mat = 0; mat < 2; mat++) {
        const int base = mat * NT_PER;
        float mx = -1e30f, sv = 0.f;
        if (tid < NT_PER) {
            mx = g_pmax[(size_t)(base + tid) * Mtot + m];
            sv = g_psum[(size_t)(base + tid) * Mtot + m];
        }
        sm[tid] = mx; __syncthreads();
        for (int s = 128; s > 0; s >>= 1) {
            if (tid < s) sm[tid] = fmaxf(sm[tid], sm[tid + s]);
            __syncthreads();
        }
        const float M = sm[0];
        ss[tid] = (tid < NT_PER) ? sv * expf(mx - M) : 0.f;
        __syncthreads();
        for (int s = 128; s > 0; s >>= 1) {
            if (tid < s) ss[tid] += ss[tid + s];
            __syncthreads();
        }
        if (tid == 0) {
            float lz = M + logf(ss[0]);
            if (mat == 0) g_lzW[m] = lz; else g_lzR[m] = lz;
        }
        __syncthreads();
    }
}

// ----------------------------------------------------------------------------
// Exact fp32 token logits: one warp per token. grid=1024, block=128
// ----------------------------------------------------------------------------
__global__ void tok_kernel(const float* __restrict__ x,
                           const float* __restrict__ W,
                           const float* __restrict__ refW,
                           const void* __restrict__ y)
{
    const int warp = threadIdx.x >> 5, lane = threadIdx.x & 31;
    const int m = blockIdx.x * 4 + warp;
    int idx = get_label(y, m);
    if (idx < 0 || idx >= Vdim) idx = 0;     // defensive clamp
    const float4* xr = reinterpret_cast<const float4*>(x    + (size_t)m   * Hdim);
    const float4* wr = reinterpret_cast<const float4*>(W    + (size_t)idx * Hdim);
    const float4* rr = reinterpret_cast<const float4*>(refW + (size_t)idx * Hdim);
    float sw = 0.f, sr = 0.f;
    for (int j = lane; j < Hdim / 4; j += 32) {
        float4 a = xr[j], b = wr[j], c = rr[j];
        sw += a.x * b.x + a.y * b.y + a.z * b.z + a.w * b.w;
        sr += a.x * c.x + a.y * c.y + a.z * c.z + a.w * c.w;
    }
#pragma unroll
    for (int o = 16; o > 0; o >>= 1) {
        sw += __shfl_xor_sync(0xffffffffu, sw, o);
        sr += __shfl_xor_sync(0xffffffffu, sr, o);
    }
    if (lane == 0) { g_tokW[m] = sw; g_tokR[m] = sr; }
}

// ----------------------------------------------------------------------------
// Final DPO scalar. one block of 512
// ----------------------------------------------------------------------------
__global__ void final_kernel(const void* __restrict__ y, float* __restrict__ out)
{
    __shared__ float red[512];
    __shared__ float pav[8], rav[8];
    const int tid = threadIdx.x;
    for (int b = 0; b < 8; b++) {
        const int m = b * 512 + tid;
        const int yv = get_label(y, m);
        const bool v = (yv != -100);
        const float p = v ? (g_tokW[m] - g_lzW[m]) : 0.f;
        const float r = v ? (g_tokR[m] - g_lzR[m]) : 0.f;
        const float c = v ? 1.f : 0.f;

        red[tid] = p; __syncthreads();
        for (int s = 256; s > 0; s >>= 1) { if (tid < s) red[tid] += red[tid + s]; __syncthreads(); }
        float ps = red[0]; __syncthreads();

        red[tid] = r; __syncthreads();
        for (int s = 256; s > 0; s >>= 1) { if (tid < s) red[tid] += red[tid + s]; __syncthreads(); }
        float rs = red[0]; __syncthreads();

        red[tid] = c; __syncthreads();
        for (int s = 256; s > 0; s >>= 1) { if (tid < s) red[tid] += red[tid + s]; __syncthreads(); }
        float cs = red[0]; __syncthreads();

        if (tid == 0) { pav[b] = ps / cs; rav[b] = rs / cs; }
        __syncthreads();
    }
    if (tid == 0) {
        float loss = 0.f;
#pragma unroll
        for (int i = 0; i < 4; i++) {
            float z = 0.1f * ((pav[i] - rav[i]) - (pav[i + 4] - rav[i + 4]));
            loss += log1pf(expf(-z));
        }
        out[0] = loss * 0.25f;
    }
}

// ----------------------------------------------------------------------------
extern "C" void kernel_launch(void* const* d_in, const int* in_sizes, int n_in,
                              void* d_out, int out_size)
{
    const float* x = nullptr;
    const void*  y = nullptr;
    const float* Wm[2] = {nullptr, nullptr};
    int wcount = 0;
    for (int i = 0; i < n_in; i++) {
        if (in_sizes[i] == 16777216)                          x = (const float*)d_in[i];
        else if (in_sizes[i] == 4096 || in_sizes[i] == 8192)  y = d_in[i];
        else if (wcount < 2)                                  Wm[wcount++] = (const float*)d_in[i];
    }
    if (!x)      x     = (const float*)d_in[0];
    if (!y)      y     = d_in[1];
    if (!Wm[0])  Wm[0] = (const float*)d_in[2];
    if (!Wm[1])  Wm[1] = (const float*)d_in[3];
    const float* W    = Wm[0];
    const float* refW = Wm[1];

    cudaFuncSetAttribute(lse_kernel, cudaFuncAttributeMaxDynamicSharedMemorySize, DSMEM);

    detect_y_kernel<<<1, 32>>>((const int*)y);
    convert_all_kernel<<<4096, 256>>>(x, W, refW);    // one launch -> lse is #3

    dim3 grid(Mtot / BM, NT_TOT);   // (32 [fast: x L2-resident], 500)
    lse_kernel<<<grid, 256, DSMEM>>>();

    reduce_lz_kernel<<<Mtot, 256>>>();
    tok_kernel<<<Mtot / 4, 128>>>(x, W, refW, y);
    final_kernel<<<1, 512>>>(y, (float*)d_out);
}